// round 6
// baseline (speedup 1.0000x reference)
#include <cuda_runtime.h>
#include <math.h>

#define B_    16
#define T_    4
#define CIN_  128
#define COUT_ 128
#define H_    56
#define W_    56
#define HW_   (H_*W_)

#define CT    32     // couts per block
#define CPT   4      // couts per thread
#define TH    2      // output rows per block
#define PX    4      // pixels per thread
#define NTHREADS 224 // 8 cout-groups x 2 rows x 14 width-groups

// dynamic smem: s_in[128][TH+2][60]  (input cols -1..56 stored at +1)
#define SROW   60
#define SCI    ((TH+2)*SROW)            // 240 floats per ci
#define SMEM_BYTES (CIN_*SCI*4)         // 122880

typedef unsigned long long u64;

// transposed weights: wT[kh][kw][ci][co]
__device__ float g_wT[9*CIN_*COUT_];

// ---------------------------------------------------------------------------
__global__ void wt_kernel(const float* __restrict__ w) {
    int i = blockIdx.x*256 + threadIdx.x;          // over co*ci*9
    if (i >= COUT_*CIN_*9) return;
    int co  = i / (CIN_*9);
    int rem = i - co*(CIN_*9);
    int ci  = rem / 9;
    int k   = rem - ci*9;
    g_wT[(k*CIN_ + ci)*COUT_ + co] = w[i];
}

// ---------------------------------------------------------------------------
// Packed fp32x2 helpers. Each lane of fma.rn.f32x2 rounds identically to
// scalar FFMA, so a packed chain == two independent scalar chains bitwise.
// ---------------------------------------------------------------------------
__device__ __forceinline__ void ffma2(u64 &d, u64 a, u64 b) {
    asm("fma.rn.f32x2 %0, %1, %2, %0;" : "+l"(d) : "l"(a), "l"(b));
}
__device__ __forceinline__ u64 pack2(float v) {
    u64 r; asm("mov.b64 %0, {%1, %1};" : "=l"(r) : "f"(v)); return r;
}
__device__ __forceinline__ u64 packf(float a, float b) {
    u64 r; asm("mov.b64 %0, {%1, %2};" : "=l"(r) : "f"(a), "f"(b)); return r;
}
__device__ __forceinline__ void unpack2(u64 v, float &lo, float &hi) {
    asm("mov.b64 {%0, %1}, %2;" : "=f"(lo), "=f"(hi) : "l"(v));
}

// ---------------------------------------------------------------------------
// Conv with reference-order sequential chain: k = (kh major, kw, ci minor),
// one fp32 accumulator per output, zero-init; bias and every elementwise op
// replicated with __f*_rn; inv via correctly-rounded 1/sqrt (XLA:CPU style).
// Block: 2 rows x 56 cols x 32 couts. Thread: 4 couts x 4 pixels x 1 row.
// ---------------------------------------------------------------------------
__global__ __launch_bounds__(NTHREADS, 1)
void conv_spike_kernel(const float* __restrict__ x,
                       const float* __restrict__ cbias,
                       const float* __restrict__ gamma,
                       const float* __restrict__ beta,
                       const float* __restrict__ rmean,
                       const float* __restrict__ rvar,
                       const float* __restrict__ alpha,
                       float* __restrict__ out)
{
    extern __shared__ __align__(16) float s_in[];  // [128][TH+2][60]

    const int ht  = blockIdx.x;        // 0..27
    const int ct  = blockIdx.y;        // 0..3
    const int b   = blockIdx.z;        // 0..15
    const int tid = threadIdx.x;       // 0..223
    const int cg  = tid / 28;          // cout group 0..7
    const int rw  = tid - cg*28;
    const int r   = rw / 14;           // row in tile 0..1
    const int wg  = rw - r*14;         // width group 0..13
    const int oh0 = ht*TH;
    const int ow0 = wg*PX;
    const int co0 = ct*CT + cg*CPT;

    // per-channel constants: inv = (1/sqrt(var+eps)) * gamma, all rn-rounded
    float cb[CPT], mn[CPT], iv[CPT], bt[CPT];
    #pragma unroll
    for (int c = 0; c < CPT; c++) {
        cb[c] = cbias[co0+c];
        mn[c] = rmean[co0+c];
        iv[c] = __fmul_rn(__fdiv_rn(1.0f, __fsqrt_rn(__fadd_rn(rvar[co0+c], 1e-5f))),
                          gamma[co0+c]);
        bt[c] = beta[co0+c];
    }

    float m[CPT][PX];                  // membrane accumulator (fp32, ascending t)

    #pragma unroll 1
    for (int t = 0; t < T_; t++) {
        const float* xbt = x + (b*T_ + t)*CIN_*HW_;

        __syncthreads();
        // stage ALL 128 input channels: 4 rows (oh0-1..oh0+2) x cols -1..56
        #pragma unroll 1
        for (int idx = tid; idx < CIN_*(TH+2)*58; idx += NTHREADS) {
            int ci  = idx / ((TH+2)*58);
            int rem = idx - ci*((TH+2)*58);
            int row = rem / 58;
            int col = rem - row*58;
            int ih = oh0 - 1 + row;
            int iw = col - 1;
            float v = 0.f;
            if ((unsigned)ih < (unsigned)H_ && (unsigned)iw < (unsigned)W_)
                v = xbt[ci*HW_ + ih*W_ + iw];
            s_in[ci*SCI + row*SROW + col] = v;
        }
        __syncthreads();

        // single fp32 accumulator per (cout,pixel), packed in cout-pairs
        u64 acc2[CPT/2][PX];
        #pragma unroll
        for (int q = 0; q < CPT/2; q++)
            #pragma unroll
            for (int p = 0; p < PX; p++) acc2[q][p] = 0ull;

        // taps outer (kh, kw), ci inner 0..127 — the reference k-order.
        #pragma unroll 1
        for (int kh = 0; kh < 3; kh++) {
            #pragma unroll 1
            for (int kw = 0; kw < 3; kw++) {
                const float* wt = g_wT + ((kh*3 + kw)*CIN_)*COUT_ + co0;
                const float* ib = s_in + (r + kh)*SROW + (ow0 + kw); // stored col = in col +1
                #pragma unroll 4
                for (int ci = 0; ci < CIN_; ci++) {
                    float4 wv = *(const float4*)(wt + ci*COUT_);
                    u64 w01 = packf(wv.x, wv.y);
                    u64 w23 = packf(wv.z, wv.w);
                    const float* ip = ib + ci*SCI;
                    #pragma unroll
                    for (int p = 0; p < PX; p++) {
                        u64 in2 = pack2(ip[p]);
                        ffma2(acc2[0][p], w01, in2);
                        ffma2(acc2[1][p], w23, in2);
                    }
                }
            }
        }

        // --- per-timestep epilogue: replicate reference fp32 roundings ---
        const float tscale = (float)(1 << (3 - t));   // exact power of 2
        #pragma unroll
        for (int c = 0; c < CPT; c++) {
            int q = c >> 1, half = c & 1;
            #pragma unroll
            for (int p = 0; p < PX; p++) {
                float al, ah;
                unpack2(acc2[q][p], al, ah);
                float y = half ? ah : al;                  // raw conv accumulator
                y = __fadd_rn(y, cb[c]);                   // + bias
                y = __fmul_rn(y, 1.875f);                  // * (2^T-1)/2^(T-1)
                y = __fmul_rn(__fsub_rn(y, mn[c]), iv[c]); // BN sub, mul
                y = __fadd_rn(y, bt[c]);                   // + beta
                y = __fdiv_rn(y, 15.0f);                   // / (2^T-1)
                float prod = __fmul_rn(y, tscale);         // exact (power of 2)
                m[c][p] = (t == 0) ? prod : __fadd_rn(m[c][p], prod);
            }
        }
    }

    // ----- spike scan (identical fp32 ops to reference) -----
    const float thr = __fdiv_rn(__fmul_rn(*alpha, 8.0f), 15.0f);
    const float coef[4] = {0.9375f, 0.875f, 0.75f, 0.5f};
    const int ohr = oh0 + r;

    #pragma unroll
    for (int c = 0; c < CPT; c++) {
        int co = co0 + c;
        float mem[PX];
        #pragma unroll
        for (int p = 0; p < PX; p++) mem[p] = m[c][p];
        float* obase = out + (b*T_*COUT_ + co)*HW_ + ohr*W_ + ow0;
        #pragma unroll
        for (int dt = 0; dt < 4; dt++) {
            float cthr = __fmul_rn(coef[dt], thr);
            float4 o;
            float s0 = (mem[0] >= cthr) ? thr : 0.f; mem[0] = __fmul_rn(__fsub_rn(mem[0], s0), 2.f);
            float s1 = (mem[1] >= cthr) ? thr : 0.f; mem[1] = __fmul_rn(__fsub_rn(mem[1], s1), 2.f);
            float s2 = (mem[2] >= cthr) ? thr : 0.f; mem[2] = __fmul_rn(__fsub_rn(mem[2], s2), 2.f);
            float s3 = (mem[3] >= cthr) ? thr : 0.f; mem[3] = __fmul_rn(__fsub_rn(mem[3], s3), 2.f);
            o.x = s0; o.y = s1; o.z = s2; o.w = s3;
            *(float4*)(obase + dt*COUT_*HW_) = o;
        }
    }
}

// ---------------------------------------------------------------------------
extern "C" void kernel_launch(void* const* d_in, const int* in_sizes, int n_in,
                              void* d_out, int out_size) {
    const float* x     = (const float*)d_in[0];
    const float* convw = (const float*)d_in[1];
    const float* convb = (const float*)d_in[2];
    const float* gamma = (const float*)d_in[3];
    const float* beta  = (const float*)d_in[4];
    const float* rmean = (const float*)d_in[5];
    const float* rvar  = (const float*)d_in[6];
    const float* alpha = (const float*)d_in[7];
    float* out = (float*)d_out;

    static int smem_set = 0;
    if (!smem_set) {
        cudaFuncSetAttribute(conv_spike_kernel,
                             cudaFuncAttributeMaxDynamicSharedMemorySize,
                             SMEM_BYTES);
        smem_set = 1;
    }

    wt_kernel<<<(COUT_*CIN_*9 + 255)/256, 256>>>(convw);

    dim3 grid(H_/TH, COUT_/CT, B_);   // 28 x 4 x 16 = 1792 CTAs
    conv_spike_kernel<<<grid, NTHREADS, SMEM_BYTES>>>(x, convb, gamma, beta,
                                                      rmean, rvar, alpha, out);
}

// round 7
// speedup vs baseline: 1.2499x; 1.2499x over previous
#include <cuda_runtime.h>
#include <math.h>

#define B_    16
#define T_    4
#define CIN_  128
#define COUT_ 128
#define H_    56
#define W_    56
#define HW_   (H_*W_)

#define CT    64     // couts per block
#define CPT   4      // couts per thread
#define PX    4      // pixels per thread
#define NTHREADS 224 // 16 cout-groups x 14 width-groups, 1 output row per CTA

// dynamic smem: s_in[128][3][60]  (rows oh0-1..oh0+1, input cols -1..56 at +1)
#define SROW   60
#define SCI    (3*SROW)                 // 180 floats per ci
#define SMEM_BYTES (CIN_*SCI*4)         // 92160 -> 2 CTAs/SM

typedef unsigned long long u64;

// transposed weights: wT[kh][kw][ci][co]
__device__ float g_wT[9*CIN_*COUT_];

// ---------------------------------------------------------------------------
__global__ void wt_kernel(const float* __restrict__ w) {
    int i = blockIdx.x*256 + threadIdx.x;          // over co*ci*9
    if (i >= COUT_*CIN_*9) return;
    int co  = i / (CIN_*9);
    int rem = i - co*(CIN_*9);
    int ci  = rem / 9;
    int k   = rem - ci*9;
    g_wT[(k*CIN_ + ci)*COUT_ + co] = w[i];
}

// ---------------------------------------------------------------------------
// Packed fp32x2 helpers. Each lane of fma.rn.f32x2 rounds identically to
// scalar FFMA, so a packed chain == two independent scalar chains bitwise.
// ---------------------------------------------------------------------------
__device__ __forceinline__ void ffma2(u64 &d, u64 a, u64 b) {
    asm("fma.rn.f32x2 %0, %1, %2, %0;" : "+l"(d) : "l"(a), "l"(b));
}
__device__ __forceinline__ u64 pack2(float v) {
    u64 r; asm("mov.b64 %0, {%1, %1};" : "=l"(r) : "f"(v)); return r;
}
__device__ __forceinline__ u64 packf(float a, float b) {
    u64 r; asm("mov.b64 %0, {%1, %2};" : "=l"(r) : "f"(a), "f"(b)); return r;
}
__device__ __forceinline__ void unpack2(u64 v, float &lo, float &hi) {
    asm("mov.b64 {%0, %1}, %2;" : "=f"(lo), "=f"(hi) : "l"(v));
}

// ---------------------------------------------------------------------------
// Conv with reference-order sequential chain: k = (kh major, kw, ci minor),
// one fp32 accumulator per output, zero-init; bias and every elementwise op
// replicated with __f*_rn; inv via correctly-rounded 1/sqrt.
// Block: 1 row x 56 cols x 64 couts. Thread: 4 couts x 4 pixels.
// 2 CTAs/SM (92KB smem each) -> 14 warps/SM; phases of the two CTAs overlap.
// ---------------------------------------------------------------------------
__global__ __launch_bounds__(NTHREADS, 2)
void conv_spike_kernel(const float* __restrict__ x,
                       const float* __restrict__ cbias,
                       const float* __restrict__ gamma,
                       const float* __restrict__ beta,
                       const float* __restrict__ rmean,
                       const float* __restrict__ rvar,
                       const float* __restrict__ alpha,
                       float* __restrict__ out)
{
    extern __shared__ __align__(16) float s_in[];  // [128][3][60]

    const int oh  = blockIdx.x;        // 0..55 (output row)
    const int ct  = blockIdx.y;        // 0..1
    const int b   = blockIdx.z;        // 0..15
    const int tid = threadIdx.x;       // 0..223
    const int cg  = tid / 14;          // cout group 0..15
    const int wg  = tid - cg*14;       // width group 0..13
    const int ow0 = wg*PX;
    const int co0 = ct*CT + cg*CPT;

    // per-channel constants: inv = (1/sqrt(var+eps)) * gamma, all rn-rounded
    float cb[CPT], mn[CPT], iv[CPT], bt[CPT];
    #pragma unroll
    for (int c = 0; c < CPT; c++) {
        cb[c] = cbias[co0+c];
        mn[c] = rmean[co0+c];
        iv[c] = __fmul_rn(__fdiv_rn(1.0f, __fsqrt_rn(__fadd_rn(rvar[co0+c], 1e-5f))),
                          gamma[co0+c]);
        bt[c] = beta[co0+c];
    }

    float m[CPT][PX];                  // membrane accumulator (fp32, ascending t)

    #pragma unroll 1
    for (int t = 0; t < T_; t++) {
        const float* xbt = x + (b*T_ + t)*CIN_*HW_;

        __syncthreads();
        // stage ALL 128 input channels: 3 rows (oh-1..oh+1) x cols -1..56
        #pragma unroll 1
        for (int idx = tid; idx < CIN_*3*58; idx += NTHREADS) {
            int ci  = idx / (3*58);
            int rem = idx - ci*(3*58);
            int row = rem / 58;
            int col = rem - row*58;
            int ih = oh - 1 + row;
            int iw = col - 1;
            float v = 0.f;
            if ((unsigned)ih < (unsigned)H_ && (unsigned)iw < (unsigned)W_)
                v = xbt[ci*HW_ + ih*W_ + iw];
            s_in[ci*SCI + row*SROW + col] = v;
        }
        __syncthreads();

        // single fp32 accumulator per (cout,pixel), packed in cout-pairs
        u64 acc2[CPT/2][PX];
        #pragma unroll
        for (int q = 0; q < CPT/2; q++)
            #pragma unroll
            for (int p = 0; p < PX; p++) acc2[q][p] = 0ull;

        // taps outer (kh, kw), ci inner 0..127 — the reference k-order.
        #pragma unroll 1
        for (int kh = 0; kh < 3; kh++) {
            #pragma unroll 1
            for (int kw = 0; kw < 3; kw++) {
                const float* wt = g_wT + ((kh*3 + kw)*CIN_)*COUT_ + co0;
                const float* ib = s_in + kh*SROW + (ow0 + kw); // stored col = in col +1
                #pragma unroll 4
                for (int ci = 0; ci < CIN_; ci++) {
                    float4 wv = *(const float4*)(wt + ci*COUT_);
                    u64 w01 = packf(wv.x, wv.y);
                    u64 w23 = packf(wv.z, wv.w);
                    const float* ip = ib + ci*SCI;
                    #pragma unroll
                    for (int p = 0; p < PX; p++) {
                        u64 in2 = pack2(ip[p]);
                        ffma2(acc2[0][p], w01, in2);
                        ffma2(acc2[1][p], w23, in2);
                    }
                }
            }
        }

        // --- per-timestep epilogue: replicate reference fp32 roundings ---
        const float tscale = (float)(1 << (3 - t));   // exact power of 2
        #pragma unroll
        for (int c = 0; c < CPT; c++) {
            int q = c >> 1, half = c & 1;
            #pragma unroll
            for (int p = 0; p < PX; p++) {
                float al, ah;
                unpack2(acc2[q][p], al, ah);
                float y = half ? ah : al;                  // raw conv accumulator
                y = __fadd_rn(y, cb[c]);                   // + bias
                y = __fmul_rn(y, 1.875f);                  // * (2^T-1)/2^(T-1)
                y = __fmul_rn(__fsub_rn(y, mn[c]), iv[c]); // BN sub, mul
                y = __fadd_rn(y, bt[c]);                   // + beta
                y = __fdiv_rn(y, 15.0f);                   // / (2^T-1)
                float prod = __fmul_rn(y, tscale);         // exact (power of 2)
                m[c][p] = (t == 0) ? prod : __fadd_rn(m[c][p], prod);
            }
        }
    }

    // ----- spike scan (identical fp32 ops to reference) -----
    const float thr = __fdiv_rn(__fmul_rn(*alpha, 8.0f), 15.0f);
    const float coef[4] = {0.9375f, 0.875f, 0.75f, 0.5f};

    #pragma unroll
    for (int c = 0; c < CPT; c++) {
        int co = co0 + c;
        float mem[PX];
        #pragma unroll
        for (int p = 0; p < PX; p++) mem[p] = m[c][p];
        float* obase = out + (b*T_*COUT_ + co)*HW_ + oh*W_ + ow0;
        #pragma unroll
        for (int dt = 0; dt < 4; dt++) {
            float cthr = __fmul_rn(coef[dt], thr);
            float4 o;
            float s0 = (mem[0] >= cthr) ? thr : 0.f; mem[0] = __fmul_rn(__fsub_rn(mem[0], s0), 2.f);
            float s1 = (mem[1] >= cthr) ? thr : 0.f; mem[1] = __fmul_rn(__fsub_rn(mem[1], s1), 2.f);
            float s2 = (mem[2] >= cthr) ? thr : 0.f; mem[2] = __fmul_rn(__fsub_rn(mem[2], s2), 2.f);
            float s3 = (mem[3] >= cthr) ? thr : 0.f; mem[3] = __fmul_rn(__fsub_rn(mem[3], s3), 2.f);
            o.x = s0; o.y = s1; o.z = s2; o.w = s3;
            *(float4*)(obase + dt*COUT_*HW_) = o;
        }
    }
}

// ---------------------------------------------------------------------------
extern "C" void kernel_launch(void* const* d_in, const int* in_sizes, int n_in,
                              void* d_out, int out_size) {
    const float* x     = (const float*)d_in[0];
    const float* convw = (const float*)d_in[1];
    const float* convb = (const float*)d_in[2];
    const float* gamma = (const float*)d_in[3];
    const float* beta  = (const float*)d_in[4];
    const float* rmean = (const float*)d_in[5];
    const float* rvar  = (const float*)d_in[6];
    const float* alpha = (const float*)d_in[7];
    float* out = (float*)d_out;

    static int smem_set = 0;
    if (!smem_set) {
        cudaFuncSetAttribute(conv_spike_kernel,
                             cudaFuncAttributeMaxDynamicSharedMemorySize,
                             SMEM_BYTES);
        smem_set = 1;
    }

    wt_kernel<<<(COUT_*CIN_*9 + 255)/256, 256>>>(convw);

    dim3 grid(H_, COUT_/CT, B_);   // 56 x 2 x 16 = 1792 CTAs
    conv_spike_kernel<<<grid, NTHREADS, SMEM_BYTES>>>(x, convb, gamma, beta,
                                                      rmean, rvar, alpha, out);
}

// round 8
// speedup vs baseline: 2.6286x; 2.1030x over previous
#include <cuda_runtime.h>
#include <math.h>

#define B_    16
#define T_    4
#define CIN_  128
#define COUT_ 128
#define H_    56
#define W_    56
#define HW_   (H_*W_)

#define CT    64     // couts per block
#define CPT   4      // couts per thread
#define PX    4      // pixels per thread
#define NTHREADS 224 // lanes: cg = tid&15 (16 couts-groups), wg = tid>>4 (14 width-groups)

// dynamic smem: one input row, duplicated f32x2: s_dup[128 ci][60 slots] of u64
// slot k holds input col (k-1), i.e. cols -1..56 at slots 0..57; 58,59 pad.
#define SROW   60
#define SMEM_BYTES (CIN_*SROW*8)        // 61440 -> 2 CTAs/SM easily

typedef unsigned long long u64;

// transposed weights: wT[kh][kw][ci][co]
__device__ float g_wT[9*CIN_*COUT_];

// ---------------------------------------------------------------------------
__global__ void wt_kernel(const float* __restrict__ w) {
    int i = blockIdx.x*256 + threadIdx.x;          // over co*ci*9
    if (i >= COUT_*CIN_*9) return;
    int co  = i / (CIN_*9);
    int rem = i - co*(CIN_*9);
    int ci  = rem / 9;
    int k   = rem - ci*9;
    g_wT[(k*CIN_ + ci)*COUT_ + co] = w[i];
}

// ---------------------------------------------------------------------------
// Packed fp32x2 helpers. Each lane of fma.rn.f32x2 rounds identically to
// scalar FFMA, so a packed chain == two independent scalar chains bitwise.
// ---------------------------------------------------------------------------
__device__ __forceinline__ void ffma2(u64 &d, u64 a, u64 b) {
    asm("fma.rn.f32x2 %0, %1, %2, %0;" : "+l"(d) : "l"(a), "l"(b));
}
__device__ __forceinline__ u64 pack2(float v) {
    u64 r; asm("mov.b64 %0, {%1, %1};" : "=l"(r) : "f"(v)); return r;
}
__device__ __forceinline__ u64 packf(float a, float b) {
    u64 r; asm("mov.b64 %0, {%1, %2};" : "=l"(r) : "f"(a), "f"(b)); return r;
}
__device__ __forceinline__ void unpack2(u64 v, float &lo, float &hi) {
    asm("mov.b64 {%0, %1}, %2;" : "=f"(lo), "=f"(hi) : "l"(v));
}

// ---------------------------------------------------------------------------
// Conv, reference-order chain k = (kh major, kw, ci minor); one fp32
// accumulator per output (packed in cout-pairs). kh outer -> stage exactly one
// duplicated input row per (t,kh). Thread: 4 couts x 4 pixels, 1 output row.
// ---------------------------------------------------------------------------
__global__ __launch_bounds__(NTHREADS, 2)
void conv_spike_kernel(const float* __restrict__ x,
                       const float* __restrict__ cbias,
                       const float* __restrict__ gamma,
                       const float* __restrict__ beta,
                       const float* __restrict__ rmean,
                       const float* __restrict__ rvar,
                       const float* __restrict__ alpha,
                       float* __restrict__ out)
{
    extern __shared__ __align__(16) u64 s_dup[];   // [128][60] f32x2

    const int oh  = blockIdx.x;        // 0..55 (output row)
    const int ct  = blockIdx.y;        // 0..1
    const int b   = blockIdx.z;        // 0..15
    const int tid = threadIdx.x;       // 0..223
    const int cg  = tid & 15;          // cout group 0..15 (fast across lanes)
    const int wg  = tid >> 4;          // width group 0..13
    const int ow0 = wg*PX;
    const int co0 = ct*CT + cg*CPT;

    // per-channel constants: inv = (1/sqrt(var+eps)) * gamma, all rn-rounded
    float cb[CPT], mn[CPT], iv[CPT], bt[CPT];
    #pragma unroll
    for (int c = 0; c < CPT; c++) {
        cb[c] = cbias[co0+c];
        mn[c] = rmean[co0+c];
        iv[c] = __fmul_rn(__fdiv_rn(1.0f, __fsqrt_rn(__fadd_rn(rvar[co0+c], 1e-5f))),
                          gamma[co0+c]);
        bt[c] = beta[co0+c];
    }

    float m[CPT][PX];                  // membrane accumulator (fp32, ascending t)

    #pragma unroll 1
    for (int t = 0; t < T_; t++) {
        const float* xbt = x + (b*T_ + t)*CIN_*HW_;

        // single fp32 accumulator per (cout,pixel), packed in cout-pairs
        u64 acc2[CPT/2][PX];
        #pragma unroll
        for (int q = 0; q < CPT/2; q++)
            #pragma unroll
            for (int p = 0; p < PX; p++) acc2[q][p] = 0ull;

        #pragma unroll 1
        for (int kh = 0; kh < 3; kh++) {
            const int ih = oh - 1 + kh;

            __syncthreads();           // previous sweep done before overwrite
            if ((unsigned)ih < (unsigned)H_) {
                // interior: 128 ci x 14 float4 groups, duplicated stores
                #pragma unroll 1
                for (int idx = tid; idx < CIN_*14; idx += NTHREADS) {
                    int ci = idx / 14;
                    int g  = idx - ci*14;
                    float4 v = *(const float4*)(xbt + ci*HW_ + ih*W_ + g*4);
                    u64* d = s_dup + ci*SROW + 1 + g*4;
                    d[0] = pack2(v.x); d[1] = pack2(v.y);
                    d[2] = pack2(v.z); d[3] = pack2(v.w);
                }
                // halo columns (-1 and 56) are zero
                #pragma unroll 1
                for (int ci = tid; ci < CIN_; ci += NTHREADS) {
                    s_dup[ci*SROW]      = 0ull;
                    s_dup[ci*SROW + 57] = 0ull;
                }
            } else {
                #pragma unroll 1
                for (int idx = tid; idx < CIN_*SROW; idx += NTHREADS)
                    s_dup[idx] = 0ull;
            }
            __syncthreads();

            // chain: kw 0..2, ci 0..127 inner (reference k-order within kh)
            #pragma unroll 1
            for (int kw = 0; kw < 3; kw++) {
                const float* wt = g_wT + ((kh*3 + kw)*CIN_)*COUT_ + co0;
                const u64*   ib = s_dup + (ow0 + kw);   // slot = col + 1 - 1 + kw... (col c at slot c+1; input col ow0+p+kw-1 -> slot ow0+p+kw)
                #pragma unroll 8
                for (int ci = 0; ci < CIN_; ci++) {
                    float4 wv = *(const float4*)(wt + ci*COUT_);
                    u64 w01 = packf(wv.x, wv.y);
                    u64 w23 = packf(wv.z, wv.w);
                    const u64* q = ib + ci*SROW;
                    u64 i0 = q[0], i1 = q[1], i2 = q[2], i3 = q[3];
                    ffma2(acc2[0][0], w01, i0); ffma2(acc2[1][0], w23, i0);
                    ffma2(acc2[0][1], w01, i1); ffma2(acc2[1][1], w23, i1);
                    ffma2(acc2[0][2], w01, i2); ffma2(acc2[1][2], w23, i2);
                    ffma2(acc2[0][3], w01, i3); ffma2(acc2[1][3], w23, i3);
                }
            }
        }

        // --- per-timestep epilogue: replicate reference fp32 roundings ---
        const float tscale = (float)(1 << (3 - t));   // exact power of 2
        #pragma unroll
        for (int c = 0; c < CPT; c++) {
            int q = c >> 1, half = c & 1;
            #pragma unroll
            for (int p = 0; p < PX; p++) {
                float al, ah;
                unpack2(acc2[q][p], al, ah);
                float y = half ? ah : al;                  // raw conv accumulator
                y = __fadd_rn(y, cb[c]);                   // + bias
                y = __fmul_rn(y, 1.875f);                  // * (2^T-1)/2^(T-1)
                y = __fmul_rn(__fsub_rn(y, mn[c]), iv[c]); // BN sub, mul
                y = __fadd_rn(y, bt[c]);                   // + beta
                y = __fdiv_rn(y, 15.0f);                   // / (2^T-1)
                float prod = __fmul_rn(y, tscale);         // exact (power of 2)
                m[c][p] = (t == 0) ? prod : __fadd_rn(m[c][p], prod);
            }
        }
    }

    // ----- spike scan (identical fp32 ops to reference) -----
    const float thr = __fdiv_rn(__fmul_rn(*alpha, 8.0f), 15.0f);
    const float coef[4] = {0.9375f, 0.875f, 0.75f, 0.5f};

    #pragma unroll
    for (int c = 0; c < CPT; c++) {
        int co = co0 + c;
        float mem[PX];
        #pragma unroll
        for (int p = 0; p < PX; p++) mem[p] = m[c][p];
        float* obase = out + (b*T_*COUT_ + co)*HW_ + oh*W_ + ow0;
        #pragma unroll
        for (int dt = 0; dt < 4; dt++) {
            float cthr = __fmul_rn(coef[dt], thr);
            float4 o;
            float s0 = (mem[0] >= cthr) ? thr : 0.f; mem[0] = __fmul_rn(__fsub_rn(mem[0], s0), 2.f);
            float s1 = (mem[1] >= cthr) ? thr : 0.f; mem[1] = __fmul_rn(__fsub_rn(mem[1], s1), 2.f);
            float s2 = (mem[2] >= cthr) ? thr : 0.f; mem[2] = __fmul_rn(__fsub_rn(mem[2], s2), 2.f);
            float s3 = (mem[3] >= cthr) ? thr : 0.f; mem[3] = __fmul_rn(__fsub_rn(mem[3], s3), 2.f);
            o.x = s0; o.y = s1; o.z = s2; o.w = s3;
            *(float4*)(obase + dt*COUT_*HW_) = o;
        }
    }
}

// ---------------------------------------------------------------------------
extern "C" void kernel_launch(void* const* d_in, const int* in_sizes, int n_in,
                              void* d_out, int out_size) {
    const float* x     = (const float*)d_in[0];
    const float* convw = (const float*)d_in[1];
    const float* convb = (const float*)d_in[2];
    const float* gamma = (const float*)d_in[3];
    const float* beta  = (const float*)d_in[4];
    const float* rmean = (const float*)d_in[5];
    const float* rvar  = (const float*)d_in[6];
    const float* alpha = (const float*)d_in[7];
    float* out = (float*)d_out;

    static int smem_set = 0;
    if (!smem_set) {
        cudaFuncSetAttribute(conv_spike_kernel,
                             cudaFuncAttributeMaxDynamicSharedMemorySize,
                             SMEM_BYTES);
        smem_set = 1;
    }

    wt_kernel<<<(COUT_*CIN_*9 + 255)/256, 256>>>(convw);

    dim3 grid(H_, COUT_/CT, B_);   // 56 x 2 x 16 = 1792 CTAs
    conv_spike_kernel<<<grid, NTHREADS, SMEM_BYTES>>>(x, convb, gamma, beta,
                                                      rmean, rvar, alpha, out);
}

// round 9
// speedup vs baseline: 2.8407x; 1.0807x over previous
#include <cuda_runtime.h>
#include <math.h>

#define B_    16
#define T_    4
#define CIN_  128
#define COUT_ 128
#define H_    56
#define W_    56
#define HW_   (H_*W_)

#define CT    64     // couts per block
#define CPT   4      // couts per thread
#define PX    4      // pixels per thread
#define NTHREADS 224 // cg = tid&15 (16 cout-groups), wg = tid>>4 (14 width-groups)

// dynamic smem: one input row, duplicated f32x2: s_dup[128 ci][60 slots] of u64
// slot k holds input col (k-1): cols -1..56 at slots 0..57; 58,59 pad.
#define SROW   60
#define SMEM_BYTES (CIN_*SROW*8)        // 61440 -> 2 CTAs/SM

typedef unsigned long long u64;

// transposed weights: wT[kh][kw][ci][co]
__device__ float g_wT[9*CIN_*COUT_];

// ---------------------------------------------------------------------------
__global__ void wt_kernel(const float* __restrict__ w) {
    int i = blockIdx.x*256 + threadIdx.x;          // over co*ci*9
    if (i >= COUT_*CIN_*9) return;
    int co  = i / (CIN_*9);
    int rem = i - co*(CIN_*9);
    int ci  = rem / 9;
    int k   = rem - ci*9;
    g_wT[(k*CIN_ + ci)*COUT_ + co] = w[i];
}

// ---------------------------------------------------------------------------
// Packed fp32x2 helpers. Each lane of fma.rn.f32x2 rounds identically to
// scalar FFMA, so a packed chain == two independent scalar chains bitwise.
// ---------------------------------------------------------------------------
__device__ __forceinline__ void ffma2(u64 &d, u64 a, u64 b) {
    asm("fma.rn.f32x2 %0, %1, %2, %0;" : "+l"(d) : "l"(a), "l"(b));
}
__device__ __forceinline__ u64 pack2(float v) {
    u64 r; asm("mov.b64 %0, {%1, %1};" : "=l"(r) : "f"(v)); return r;
}
__device__ __forceinline__ void unpack2(u64 v, float &lo, float &hi) {
    asm("mov.b64 {%0, %1}, %2;" : "=f"(lo), "=f"(hi) : "l"(v));
}

// one ci step: 1 weight LDG.128 (as ulonglong2 -> two f32x2 pairs, zero MOVs)
// + input slots i0..i3 + 8 FFMA2 into the 8 accumulators.
#define CI_STEP(WP, I0, I1, I2, I3)                                   \
    do {                                                              \
        ffma2(acc2[0][0], (WP).x, (I0)); ffma2(acc2[1][0], (WP).y, (I0)); \
        ffma2(acc2[0][1], (WP).x, (I1)); ffma2(acc2[1][1], (WP).y, (I1)); \
        ffma2(acc2[0][2], (WP).x, (I2)); ffma2(acc2[1][2], (WP).y, (I2)); \
        ffma2(acc2[0][3], (WP).x, (I3)); ffma2(acc2[1][3], (WP).y, (I3)); \
    } while (0)

// ---------------------------------------------------------------------------
// Conv, reference-order chain k = (kh major, kw, ci minor); one fp32
// accumulator per output (packed in cout-pairs). kh outer -> stage exactly one
// duplicated input row per (t,kh). Thread: 4 couts x 4 pixels, 1 output row.
// ---------------------------------------------------------------------------
__global__ __launch_bounds__(NTHREADS, 2)
void conv_spike_kernel(const float* __restrict__ x,
                       const float* __restrict__ cbias,
                       const float* __restrict__ gamma,
                       const float* __restrict__ beta,
                       const float* __restrict__ rmean,
                       const float* __restrict__ rvar,
                       const float* __restrict__ alpha,
                       float* __restrict__ out)
{
    extern __shared__ __align__(16) u64 s_dup[];   // [128][60] f32x2

    const int oh  = blockIdx.x;        // 0..55 (output row)
    const int ct  = blockIdx.y;        // 0..1
    const int b   = blockIdx.z;        // 0..15
    const int tid = threadIdx.x;       // 0..223
    const int cg  = tid & 15;          // cout group 0..15 (fast across lanes)
    const int wg  = tid >> 4;          // width group 0..13
    const int ow0 = wg*PX;
    const int co0 = ct*CT + cg*CPT;

    // per-channel constants: inv = (1/sqrt(var+eps)) * gamma, all rn-rounded
    float cb[CPT], mn[CPT], iv[CPT], bt[CPT];
    #pragma unroll
    for (int c = 0; c < CPT; c++) {
        cb[c] = cbias[co0+c];
        mn[c] = rmean[co0+c];
        iv[c] = __fmul_rn(__fdiv_rn(1.0f, __fsqrt_rn(__fadd_rn(rvar[co0+c], 1e-5f))),
                          gamma[co0+c]);
        bt[c] = beta[co0+c];
    }

    float m[CPT][PX];                  // membrane accumulator (fp32, ascending t)

    #pragma unroll 1
    for (int t = 0; t < T_; t++) {
        const float* xbt = x + (b*T_ + t)*CIN_*HW_;

        // single fp32 accumulator per (cout,pixel), packed in cout-pairs
        u64 acc2[CPT/2][PX];
        #pragma unroll
        for (int q = 0; q < CPT/2; q++)
            #pragma unroll
            for (int p = 0; p < PX; p++) acc2[q][p] = 0ull;

        #pragma unroll 1
        for (int kh = 0; kh < 3; kh++) {
            const int ih = oh - 1 + kh;

            __syncthreads();           // previous sweep done before overwrite
            if ((unsigned)ih < (unsigned)H_) {
                // interior: 128 ci x 14 float4 groups, duplicated stores
                #pragma unroll 1
                for (int idx = tid; idx < CIN_*14; idx += NTHREADS) {
                    int ci = idx / 14;
                    int g  = idx - ci*14;
                    float4 v = *(const float4*)(xbt + ci*HW_ + ih*W_ + g*4);
                    u64* d = s_dup + ci*SROW + 1 + g*4;
                    d[0] = pack2(v.x); d[1] = pack2(v.y);
                    d[2] = pack2(v.z); d[3] = pack2(v.w);
                }
                // halo columns (-1 and 56) are zero
                #pragma unroll 1
                for (int ci = tid; ci < CIN_; ci += NTHREADS) {
                    s_dup[ci*SROW]      = 0ull;
                    s_dup[ci*SROW + 57] = 0ull;
                }
            } else {
                #pragma unroll 1
                for (int idx = tid; idx < CIN_*SROW; idx += NTHREADS)
                    s_dup[idx] = 0ull;
            }
            __syncthreads();

            // chain: kw 0..2 in order, ci 0..127 inner (reference k-order).
            // kw-specialized loops so input fetches are LDS.128 where aligned.
            {   // kw = 0: slots ow0..ow0+3, 16B-aligned
                const float* wt = g_wT + ((kh*3 + 0)*CIN_)*COUT_ + co0;
                const u64*   ib = s_dup + ow0;
                #pragma unroll 8
                for (int ci = 0; ci < CIN_; ci++) {
                    ulonglong2 wp = *(const ulonglong2*)(wt + ci*COUT_);
                    const u64* q = ib + ci*SROW;
                    ulonglong2 v01 = *(const ulonglong2*)(q);
                    ulonglong2 v23 = *(const ulonglong2*)(q + 2);
                    CI_STEP(wp, v01.x, v01.y, v23.x, v23.y);
                }
            }
            {   // kw = 1: slots ow0+1..ow0+4 via 3x LDS.128 (use 4 of 6)
                const float* wt = g_wT + ((kh*3 + 1)*CIN_)*COUT_ + co0;
                const u64*   ib = s_dup + ow0;
                #pragma unroll 8
                for (int ci = 0; ci < CIN_; ci++) {
                    ulonglong2 wp = *(const ulonglong2*)(wt + ci*COUT_);
                    const u64* q = ib + ci*SROW;
                    ulonglong2 v01 = *(const ulonglong2*)(q);
                    ulonglong2 v23 = *(const ulonglong2*)(q + 2);
                    ulonglong2 v45 = *(const ulonglong2*)(q + 4);
                    CI_STEP(wp, v01.y, v23.x, v23.y, v45.x);
                }
            }
            {   // kw = 2: slots ow0+2..ow0+5, 16B-aligned
                const float* wt = g_wT + ((kh*3 + 2)*CIN_)*COUT_ + co0;
                const u64*   ib = s_dup + ow0 + 2;
                #pragma unroll 8
                for (int ci = 0; ci < CIN_; ci++) {
                    ulonglong2 wp = *(const ulonglong2*)(wt + ci*COUT_);
                    const u64* q = ib + ci*SROW;
                    ulonglong2 v01 = *(const ulonglong2*)(q);
                    ulonglong2 v23 = *(const ulonglong2*)(q + 2);
                    CI_STEP(wp, v01.x, v01.y, v23.x, v23.y);
                }
            }
        }

        // --- per-timestep epilogue: replicate reference fp32 roundings ---
        const float tscale = (float)(1 << (3 - t));   // exact power of 2
        #pragma unroll
        for (int c = 0; c < CPT; c++) {
            int q = c >> 1, half = c & 1;
            #pragma unroll
            for (int p = 0; p < PX; p++) {
                float al, ah;
                unpack2(acc2[q][p], al, ah);
                float y = half ? ah : al;                  // raw conv accumulator
                y = __fadd_rn(y, cb[c]);                   // + bias
                y = __fmul_rn(y, 1.875f);                  // * (2^T-1)/2^(T-1)
                y = __fmul_rn(__fsub_rn(y, mn[c]), iv[c]); // BN sub, mul
                y = __fadd_rn(y, bt[c]);                   // + beta
                y = __fdiv_rn(y, 15.0f);                   // / (2^T-1)
                float prod = __fmul_rn(y, tscale);         // exact (power of 2)
                m[c][p] = (t == 0) ? prod : __fadd_rn(m[c][p], prod);
            }
        }
    }

    // ----- spike scan (identical fp32 ops to reference) -----
    const float thr = __fdiv_rn(__fmul_rn(*alpha, 8.0f), 15.0f);
    const float coef[4] = {0.9375f, 0.875f, 0.75f, 0.5f};

    #pragma unroll
    for (int c = 0; c < CPT; c++) {
        int co = co0 + c;
        float mem[PX];
        #pragma unroll
        for (int p = 0; p < PX; p++) mem[p] = m[c][p];
        float* obase = out + (b*T_*COUT_ + co)*HW_ + oh*W_ + ow0;
        #pragma unroll
        for (int dt = 0; dt < 4; dt++) {
            float cthr = __fmul_rn(coef[dt], thr);
            float4 o;
            float s0 = (mem[0] >= cthr) ? thr : 0.f; mem[0] = __fmul_rn(__fsub_rn(mem[0], s0), 2.f);
            float s1 = (mem[1] >= cthr) ? thr : 0.f; mem[1] = __fmul_rn(__fsub_rn(mem[1], s1), 2.f);
            float s2 = (mem[2] >= cthr) ? thr : 0.f; mem[2] = __fmul_rn(__fsub_rn(mem[2], s2), 2.f);
            float s3 = (mem[3] >= cthr) ? thr : 0.f; mem[3] = __fmul_rn(__fsub_rn(mem[3], s3), 2.f);
            o.x = s0; o.y = s1; o.z = s2; o.w = s3;
            *(float4*)(obase + dt*COUT_*HW_) = o;
        }
    }
}

// ---------------------------------------------------------------------------
extern "C" void kernel_launch(void* const* d_in, const int* in_sizes, int n_in,
                              void* d_out, int out_size) {
    const float* x     = (const float*)d_in[0];
    const float* convw = (const float*)d_in[1];
    const float* convb = (const float*)d_in[2];
    const float* gamma = (const float*)d_in[3];
    const float* beta  = (const float*)d_in[4];
    const float* rmean = (const float*)d_in[5];
    const float* rvar  = (const float*)d_in[6];
    const float* alpha = (const float*)d_in[7];
    float* out = (float*)d_out;

    static int smem_set = 0;
    if (!smem_set) {
        cudaFuncSetAttribute(conv_spike_kernel,
                             cudaFuncAttributeMaxDynamicSharedMemorySize,
                             SMEM_BYTES);
        smem_set = 1;
    }

    wt_kernel<<<(COUT_*CIN_*9 + 255)/256, 256>>>(convw);

    dim3 grid(H_, COUT_/CT, B_);   // 56 x 2 x 16 = 1792 CTAs
    conv_spike_kernel<<<grid, NTHREADS, SMEM_BYTES>>>(x, convb, gamma, beta,
                                                      rmean, rvar, alpha, out);
}

// round 10
// speedup vs baseline: 3.3441x; 1.1772x over previous
#include <cuda_runtime.h>
#include <math.h>

#define B_    16
#define T_    4
#define CIN_  128
#define COUT_ 128
#define H_    56
#define W_    56
#define HW_   (H_*W_)

#define CT    64     // couts per block
#define CPT   4      // couts per thread
#define PX    4      // pixels per thread
#define NTHREADS 224 // cg = tid&15 (16 cout-groups), wg = tid>>4 (14 width-groups)

// dynamic smem: one scalar input row: s_in[128 ci][60]
// index k holds input col (k-1): cols -1..56 at idx 0..57; 58,59 pad.
// ow0 = wg*4 -> idx ow0 is 16B-aligned (kw0 window ow0-1..ow0+2 = idx ow0..ow0+3).
#define SROW   60
#define SMEM_BYTES (CIN_*SROW*4)        // 30720 -> 2 CTAs/SM with room

typedef unsigned long long u64;

// transposed weights: wT[kh][kw][ci][co]
__device__ float g_wT[9*CIN_*COUT_];

// ---------------------------------------------------------------------------
__global__ void wt_kernel(const float* __restrict__ w) {
    int i = blockIdx.x*256 + threadIdx.x;          // over co*ci*9
    if (i >= COUT_*CIN_*9) return;
    int co  = i / (CIN_*9);
    int rem = i - co*(CIN_*9);
    int ci  = rem / 9;
    int k   = rem - ci*9;
    g_wT[(k*CIN_ + ci)*COUT_ + co] = w[i];
}

// ---------------------------------------------------------------------------
// Packed fp32x2 helpers. Each lane of fma.rn.f32x2 rounds identically to
// scalar FFMA, so a packed chain == two independent scalar chains bitwise.
// ---------------------------------------------------------------------------
__device__ __forceinline__ void ffma2(u64 &d, u64 a, u64 b) {
    asm("fma.rn.f32x2 %0, %1, %2, %0;" : "+l"(d) : "l"(a), "l"(b));
}
__device__ __forceinline__ u64 pack2(float v) {   // {v, v} — 1 MOV in SASS
    u64 r; asm("mov.b64 %0, {%1, %1};" : "=l"(r) : "f"(v)); return r;
}
__device__ __forceinline__ void unpack2(u64 v, float &lo, float &hi) {
    asm("mov.b64 {%0, %1}, %2;" : "=f"(lo), "=f"(hi) : "l"(v));
}

// one ci step: weight pair (two f32x2) x 4 dup'd input pixels -> 8 FFMA2
#define CI_STEP(WP, I0, I1, I2, I3)                                       \
    do {                                                                  \
        ffma2(acc2[0][0], (WP).x, (I0)); ffma2(acc2[1][0], (WP).y, (I0)); \
        ffma2(acc2[0][1], (WP).x, (I1)); ffma2(acc2[1][1], (WP).y, (I1)); \
        ffma2(acc2[0][2], (WP).x, (I2)); ffma2(acc2[1][2], (WP).y, (I2)); \
        ffma2(acc2[0][3], (WP).x, (I3)); ffma2(acc2[1][3], (WP).y, (I3)); \
    } while (0)

// ---------------------------------------------------------------------------
// Conv, reference-order chain k = (kh major, kw, ci minor); one fp32
// accumulator per output (packed in cout-pairs). kh outer -> stage exactly one
// scalar input row per (t,kh). Thread: 4 couts x 4 pixels, 1 output row.
// ---------------------------------------------------------------------------
__global__ __launch_bounds__(NTHREADS, 2)
void conv_spike_kernel(const float* __restrict__ x,
                       const float* __restrict__ cbias,
                       const float* __restrict__ gamma,
                       const float* __restrict__ beta,
                       const float* __restrict__ rmean,
                       const float* __restrict__ rvar,
                       const float* __restrict__ alpha,
                       float* __restrict__ out)
{
    extern __shared__ __align__(16) float s_in[];  // [128][60] scalar

    const int oh  = blockIdx.x;        // 0..55 (output row)
    const int ct  = blockIdx.y;        // 0..1
    const int b   = blockIdx.z;        // 0..15
    const int tid = threadIdx.x;       // 0..223
    const int cg  = tid & 15;          // cout group 0..15 (fast across lanes)
    const int wg  = tid >> 4;          // width group 0..13
    const int ow0 = wg*PX;
    const int co0 = ct*CT + cg*CPT;

    // per-channel constants: inv = (1/sqrt(var+eps)) * gamma, all rn-rounded
    float cb[CPT], mn[CPT], iv[CPT], bt[CPT];
    #pragma unroll
    for (int c = 0; c < CPT; c++) {
        cb[c] = cbias[co0+c];
        mn[c] = rmean[co0+c];
        iv[c] = __fmul_rn(__fdiv_rn(1.0f, __fsqrt_rn(__fadd_rn(rvar[co0+c], 1e-5f))),
                          gamma[co0+c]);
        bt[c] = beta[co0+c];
    }

    float m[CPT][PX];                  // membrane accumulator (fp32, ascending t)

    #pragma unroll 1
    for (int t = 0; t < T_; t++) {
        const float* xbt = x + (b*T_ + t)*CIN_*HW_;

        // single fp32 accumulator per (cout,pixel), packed in cout-pairs
        u64 acc2[CPT/2][PX];
        #pragma unroll
        for (int q = 0; q < CPT/2; q++)
            #pragma unroll
            for (int p = 0; p < PX; p++) acc2[q][p] = 0ull;

        #pragma unroll 1
        for (int kh = 0; kh < 3; kh++) {
            const int ih = oh - 1 + kh;

            __syncthreads();           // previous sweep done before overwrite
            if ((unsigned)ih < (unsigned)H_) {
                // interior: 128 ci x 14 float4 gmem reads, scalar smem stores
                #pragma unroll 1
                for (int idx = tid; idx < CIN_*14; idx += NTHREADS) {
                    int ci = idx / 14;
                    int g  = idx - ci*14;
                    float4 v = *(const float4*)(xbt + ci*HW_ + ih*W_ + g*4);
                    float* d = s_in + ci*SROW + 1 + g*4;
                    d[0] = v.x; d[1] = v.y; d[2] = v.z; d[3] = v.w;
                }
                // halo columns (-1 at idx 0, 56 at idx 57) are zero
                #pragma unroll 1
                for (int ci = tid; ci < CIN_; ci += NTHREADS) {
                    s_in[ci*SROW]      = 0.f;
                    s_in[ci*SROW + 57] = 0.f;
                }
            } else {
                #pragma unroll 1
                for (int idx = tid; idx < CIN_*SROW; idx += NTHREADS)
                    s_in[idx] = 0.f;
            }
            __syncthreads();

            // chain: kw 0..2 in order, ci 0..127 inner (reference k-order).
            {   // kw = 0: idx ow0..ow0+3, 16B-aligned -> 1 LDS.128
                const float* wt = g_wT + ((kh*3 + 0)*CIN_)*COUT_ + co0;
                const float* ib = s_in + ow0;
                #pragma unroll 8
                for (int ci = 0; ci < CIN_; ci++) {
                    ulonglong2 wp = *(const ulonglong2*)(wt + ci*COUT_);
                    float4 v = *(const float4*)(ib + ci*SROW);
                    CI_STEP(wp, pack2(v.x), pack2(v.y), pack2(v.z), pack2(v.w));
                }
            }
            {   // kw = 1: idx ow0+1..ow0+4 -> LDS.128 (use .y.z.w) + LDS.32
                const float* wt = g_wT + ((kh*3 + 1)*CIN_)*COUT_ + co0;
                const float* ib = s_in + ow0;
                #pragma unroll 8
                for (int ci = 0; ci < CIN_; ci++) {
                    ulonglong2 wp = *(const ulonglong2*)(wt + ci*COUT_);
                    float4 v = *(const float4*)(ib + ci*SROW);
                    float  s4 = ib[ci*SROW + 4];
                    CI_STEP(wp, pack2(v.y), pack2(v.z), pack2(v.w), pack2(s4));
                }
            }
            {   // kw = 2: idx ow0+2..ow0+5 -> 2x LDS.64 (8B-aligned)
                const float* wt = g_wT + ((kh*3 + 2)*CIN_)*COUT_ + co0;
                const float* ib = s_in + ow0 + 2;
                #pragma unroll 8
                for (int ci = 0; ci < CIN_; ci++) {
                    ulonglong2 wp = *(const ulonglong2*)(wt + ci*COUT_);
                    float2 v01 = *(const float2*)(ib + ci*SROW);
                    float2 v23 = *(const float2*)(ib + ci*SROW + 2);
                    CI_STEP(wp, pack2(v01.x), pack2(v01.y), pack2(v23.x), pack2(v23.y));
                }
            }
        }

        // --- per-timestep epilogue: replicate reference fp32 roundings ---
        const float tscale = (float)(1 << (3 - t));   // exact power of 2
        #pragma unroll
        for (int c = 0; c < CPT; c++) {
            int q = c >> 1, half = c & 1;
            #pragma unroll
            for (int p = 0; p < PX; p++) {
                float al, ah;
                unpack2(acc2[q][p], al, ah);
                float y = half ? ah : al;                  // raw conv accumulator
                y = __fadd_rn(y, cb[c]);                   // + bias
                y = __fmul_rn(y, 1.875f);                  // * (2^T-1)/2^(T-1)
                y = __fmul_rn(__fsub_rn(y, mn[c]), iv[c]); // BN sub, mul
                y = __fadd_rn(y, bt[c]);                   // + beta
                y = __fdiv_rn(y, 15.0f);                   // / (2^T-1)
                float prod = __fmul_rn(y, tscale);         // exact (power of 2)
                m[c][p] = (t == 0) ? prod : __fadd_rn(m[c][p], prod);
            }
        }
    }

    // ----- spike scan (identical fp32 ops to reference) -----
    const float thr = __fdiv_rn(__fmul_rn(*alpha, 8.0f), 15.0f);
    const float coef[4] = {0.9375f, 0.875f, 0.75f, 0.5f};

    #pragma unroll
    for (int c = 0; c < CPT; c++) {
        int co = co0 + c;
        float mem[PX];
        #pragma unroll
        for (int p = 0; p < PX; p++) mem[p] = m[c][p];
        float* obase = out + (b*T_*COUT_ + co)*HW_ + oh*W_ + ow0;
        #pragma unroll
        for (int dt = 0; dt < 4; dt++) {
            float cthr = __fmul_rn(coef[dt], thr);
            float4 o;
            float s0 = (mem[0] >= cthr) ? thr : 0.f; mem[0] = __fmul_rn(__fsub_rn(mem[0], s0), 2.f);
            float s1 = (mem[1] >= cthr) ? thr : 0.f; mem[1] = __fmul_rn(__fsub_rn(mem[1], s1), 2.f);
            float s2 = (mem[2] >= cthr) ? thr : 0.f; mem[2] = __fmul_rn(__fsub_rn(mem[2], s2), 2.f);
            float s3 = (mem[3] >= cthr) ? thr : 0.f; mem[3] = __fmul_rn(__fsub_rn(mem[3], s3), 2.f);
            o.x = s0; o.y = s1; o.z = s2; o.w = s3;
            *(float4*)(obase + dt*COUT_*HW_) = o;
        }
    }
}

// ---------------------------------------------------------------------------
extern "C" void kernel_launch(void* const* d_in, const int* in_sizes, int n_in,
                              void* d_out, int out_size) {
    const float* x     = (const float*)d_in[0];
    const float* convw = (const float*)d_in[1];
    const float* convb = (const float*)d_in[2];
    const float* gamma = (const float*)d_in[3];
    const float* beta  = (const float*)d_in[4];
    const float* rmean = (const float*)d_in[5];
    const float* rvar  = (const float*)d_in[6];
    const float* alpha = (const float*)d_in[7];
    float* out = (float*)d_out;

    wt_kernel<<<(COUT_*CIN_*9 + 255)/256, 256>>>(convw);

    dim3 grid(H_, COUT_/CT, B_);   // 56 x 2 x 16 = 1792 CTAs
    conv_spike_kernel<<<grid, NTHREADS, SMEM_BYTES>>>(x, convb, gamma, beta,
                                                      rmean, rvar, alpha, out);
}